// round 1
// baseline (speedup 1.0000x reference)
#include <cuda_runtime.h>
#include <cstdint>

// Dilution 2x: x [8,3,512,512] f32 -> out [8,3,1024,1024] f32
// out[b,c,2y,2x] = x[b,c,y,x]; all other outputs 0.
//
// Single pass over the output, one float4 store per thread.
// Output float4 at (plane, row, col4) covers output cols [4*col4, 4*col4+3].
//   row even: v = { in[row/2][2*col4], 0, in[row/2][2*col4+1], 0 }
//   row odd : v = 0
// Each 256-thread block maps to exactly one output row -> uniform branch per block.

static constexpr int HF = 512, WF = 512;
static constexpr int HT = 1024, WT = 1024;
static constexpr int PLANES = 8 * 3;
static constexpr int F4_PER_ROW = WT / 4;              // 256
static constexpr int TOTAL_F4 = PLANES * HT * F4_PER_ROW;  // 6,291,456

__global__ void __launch_bounds__(256)
dilution_kernel(const float* __restrict__ in, float4* __restrict__ out) {
    unsigned idx = blockIdx.x * 256u + threadIdx.x;   // one float4 of output
    // decompose (power-of-two -> shifts)
    unsigned col4  = idx & (F4_PER_ROW - 1);          // idx % 256
    unsigned row   = (idx >> 8) & (HT - 1);           // (idx/256) % 1024
    unsigned plane = idx >> 18;                       // idx / (256*1024)

    float4 v = make_float4(0.f, 0.f, 0.f, 0.f);
    if ((row & 1u) == 0u) {
        const float2* inrow =
            reinterpret_cast<const float2*>(in + ((size_t)plane * HF + (row >> 1)) * WF);
        float2 a = __ldg(&inrow[col4]);               // input cols 2*col4, 2*col4+1
        v.x = a.x;
        v.z = a.y;
    }
    out[idx] = v;
}

extern "C" void kernel_launch(void* const* d_in, const int* in_sizes, int n_in,
                              void* d_out, int out_size) {
    (void)in_sizes; (void)n_in; (void)out_size;
    const float* x = (const float*)d_in[0];
    float4* out = (float4*)d_out;
    dilution_kernel<<<TOTAL_F4 / 256, 256>>>(x, out);
}